// round 13
// baseline (speedup 1.0000x reference)
#include <cuda_runtime.h>
#include <stdint.h>

// carry_save_adder: exact-binary reduction.  [FINAL — champion config R8]
// S_b = sum over kept i of value(x[b,i,:]); out bits = S_b & 0xFFFF, carry = S_b >> 16.
// Non-persistent in-order CTAs (HW bid-order rasterization beats every software
// schedule tested), 512 thr = 16 rows per CTA, one warp per row.
// Loads: ld.global.nc + L2::256B fetch granularity + evict_first cache policy.
// FFMA-imm nibble accumulation with the loop-invariant weight 2^((lane&3)*4)
// factored out; exact fp32 arithmetic (S < 2^22); 5-shuffle warp reduce.
// Measured: 23.26us ncu, 5.93 TB/s (~75% of 8TB/s spec = HBM3e stream ceiling).

__device__ __forceinline__ float4 ldg_stream(const float4* p, unsigned long long pol) {
    float4 v;
    asm("ld.global.nc.L2::cache_hint.L2::256B.v4.f32 {%0,%1,%2,%3}, [%4], %5;"
        : "=f"(v.x), "=f"(v.y), "=f"(v.z), "=f"(v.w)
        : "l"(p), "l"(pol));
    return v;
}

__global__ void __launch_bounds__(512)
csa_kernel(const float4* __restrict__ x, const int* __restrict__ mask,
           float* __restrict__ out, int B)
{
    const unsigned FULL = 0xFFFFFFFFu;
    const int lane = threadIdx.x & 31;
    const int warp = (blockIdx.x << 4) + (threadIdx.x >> 5);
    if (warp >= B) return;

    unsigned long long pol;
    asm("createpolicy.fractional.L2::evict_first.b64 %0, 1.0;" : "=l"(pol));

    // Keep mask over the 64 values (indices 0,1 always kept).
    const unsigned mb_lo = __ballot_sync(FULL, mask[lane]      > 0) | 3u;
    const unsigned mb_hi = __ballot_sync(FULL, mask[lane + 32] > 0);

    // Chunk t of this lane holds value index i = 8t + (lane>>2); keep weight:
    const unsigned q = (unsigned)lane >> 2;
    float keepf[8];
    #pragma unroll
    for (int t = 0; t < 8; ++t) {
        unsigned bit = (t < 4) ? ((mb_lo >> (8 * t + q)) & 1u)
                               : ((mb_hi >> (8 * (t - 4) + q)) & 1u);
        keepf[t] = bit ? 1.0f : 0.0f;
    }
    // Loop-invariant nibble weight 2^((lane&3)*4).
    const float wgt = __int_as_float((127 + (((int)lane & 3) << 2)) << 23);

    const float4* row = x + (size_t)warp * 256;

    float sumf = 0.0f;
    #pragma unroll
    for (int t = 0; t < 8; ++t) {
        float4 v = ldg_stream(&row[lane + (t << 5)], pol);
        float part = v.x;
        part = fmaf(v.y, 2.0f, part);
        part = fmaf(v.z, 4.0f, part);
        part = fmaf(v.w, 8.0f, part);
        sumf = fmaf(part, keepf[t], sumf);
    }
    sumf *= wgt;

    // Warp reduction (exact: integer-valued floats, total < 2^22).
    #pragma unroll
    for (int off = 16; off; off >>= 1)
        sumf += __shfl_xor_sync(FULL, sumf, off);

    const unsigned s = (unsigned)sumf;
    if (lane < 16)
        out[(size_t)warp * 16 + lane] = (float)((s >> lane) & 1u);
    else if (lane == 16)
        out[(size_t)B * 16 + warp] = (float)(s >> 16);
}

extern "C" void kernel_launch(void* const* d_in, const int* in_sizes, int n_in,
                              void* d_out, int out_size)
{
    const float4* x   = (const float4*)d_in[0];   // (B, 64, 16) float32
    const int*    msk = (const int*)d_in[1];      // (64,) int32
    float*        out = (float*)d_out;            // B*16 output bits, then B carries

    int B = in_sizes[0] / 1024;                   // 64*16 floats per batch row
    int blocks = (B + 15) / 16;                   // 16 rows per 512-thread CTA
    csa_kernel<<<blocks, 512>>>(x, msk, out, B);
}

// round 14
// speedup vs baseline: 1.0013x; 1.0013x over previous
#include <cuda_runtime.h>
#include <stdint.h>

// carry_save_adder: exact-binary reduction.  [FINAL — champion config R8]
// The reference's float-encoded boolean CSA network reduces exactly to:
//   S_b = sum over kept i of value(x[b,i,:]) with value = sum_j x[b,i,j]*2^j;
//   output[b,j] = (S_b >> j) & 1 (j<16), carry[b] = S_b >> 16.  (S < 2^22, exact fp32.)
// Non-persistent in-order CTAs (HW bid-order rasterization beat every software
// schedule tested: persistent/grid-stride/TMA/prefetch all regressed DRAM%),
// 512 thr = 16 rows per CTA, one warp per row.
// Loads: ld.global.nc + L2::256B fetch granularity + evict_first cache policy.
// FFMA-imm nibble accumulation with the loop-invariant weight 2^((lane&3)*4)
// factored out; 5-shuffle warp reduce; 17 float stores per row.
// Measured: 23.3us ncu, 5.9 TB/s = ~75% of 8TB/s spec (HBM3e stream ceiling).

__device__ __forceinline__ float4 ldg_stream(const float4* p, unsigned long long pol) {
    float4 v;
    asm("ld.global.nc.L2::cache_hint.L2::256B.v4.f32 {%0,%1,%2,%3}, [%4], %5;"
        : "=f"(v.x), "=f"(v.y), "=f"(v.z), "=f"(v.w)
        : "l"(p), "l"(pol));
    return v;
}

__global__ void __launch_bounds__(512)
csa_kernel(const float4* __restrict__ x, const int* __restrict__ mask,
           float* __restrict__ out, int B)
{
    const unsigned FULL = 0xFFFFFFFFu;
    const int lane = threadIdx.x & 31;
    const int warp = (blockIdx.x << 4) + (threadIdx.x >> 5);
    if (warp >= B) return;

    unsigned long long pol;
    asm("createpolicy.fractional.L2::evict_first.b64 %0, 1.0;" : "=l"(pol));

    // Keep mask over the 64 values (indices 0,1 always kept).
    const unsigned mb_lo = __ballot_sync(FULL, mask[lane]      > 0) | 3u;
    const unsigned mb_hi = __ballot_sync(FULL, mask[lane + 32] > 0);

    // Chunk t of this lane holds value index i = 8t + (lane>>2); keep weight:
    const unsigned q = (unsigned)lane >> 2;
    float keepf[8];
    #pragma unroll
    for (int t = 0; t < 8; ++t) {
        unsigned bit = (t < 4) ? ((mb_lo >> (8 * t + q)) & 1u)
                               : ((mb_hi >> (8 * (t - 4) + q)) & 1u);
        keepf[t] = bit ? 1.0f : 0.0f;
    }
    // Loop-invariant nibble weight 2^((lane&3)*4).
    const float wgt = __int_as_float((127 + (((int)lane & 3) << 2)) << 23);

    const float4* row = x + (size_t)warp * 256;

    float sumf = 0.0f;
    #pragma unroll
    for (int t = 0; t < 8; ++t) {
        float4 v = ldg_stream(&row[lane + (t << 5)], pol);
        float part = v.x;
        part = fmaf(v.y, 2.0f, part);
        part = fmaf(v.z, 4.0f, part);
        part = fmaf(v.w, 8.0f, part);
        sumf = fmaf(part, keepf[t], sumf);
    }
    sumf *= wgt;

    // Warp reduction (exact: integer-valued floats, total < 2^22).
    #pragma unroll
    for (int off = 16; off; off >>= 1)
        sumf += __shfl_xor_sync(FULL, sumf, off);

    const unsigned s = (unsigned)sumf;
    if (lane < 16)
        out[(size_t)warp * 16 + lane] = (float)((s >> lane) & 1u);
    else if (lane == 16)
        out[(size_t)B * 16 + warp] = (float)(s >> 16);
}

extern "C" void kernel_launch(void* const* d_in, const int* in_sizes, int n_in,
                              void* d_out, int out_size)
{
    const float4* x   = (const float4*)d_in[0];   // (B, 64, 16) float32
    const int*    msk = (const int*)d_in[1];      // (64,) int32
    float*        out = (float*)d_out;            // B*16 output bits, then B carries

    int B = in_sizes[0] / 1024;                   // 64*16 floats per batch row
    int blocks = (B + 15) / 16;                   // 16 rows per 512-thread CTA
    csa_kernel<<<blocks, 512>>>(x, msk, out, B);
}